// round 6
// baseline (speedup 1.0000x reference)
#include <cuda_runtime.h>
#include <stdint.h>

// MultiLevelHybridHashEncoding — instant-NGP hash-grid encoding.
// R5 -> R6: drop smem staging (keep L1D carveout at full 228 KB so the three
// coarse dense tables ~221 KB stay L1-resident), drop the persistent loop +
// prefetch, remove the LDS/LDG divergence (all 16 levels in one 32-lane LDG
// per corner batch). One item per thread, 32 lanes = 1 point (16 levels x
// 2 x-halves), pair-coalesced gathers, shfl pair-reduce, coalesced stores.
// __launch_bounds__(256,7) -> <=36 regs -> 56 warps/SM.

#define NLEVELS 16

struct Params {
    const float2* tab[NLEVELS];
};

__device__ __constant__ int c_res[NLEVELS] = {
    16, 20, 25, 32, 40, 50, 64, 80, 101, 128, 161, 203, 256, 322, 406, 512
};

#define P1 2654435761u
#define P2 805459861u
#define HMASK 0x7FFFFu

__global__ void __launch_bounds__(256, 7)
hashenc_kernel(const float* __restrict__ x, Params p,
               float2* __restrict__ out, int B)
{
    const int tid = blockIdx.x * 256 + threadIdx.x;
    const int b = tid >> 5;                     // warp -> point
    if (b >= B) return;

    const int ox = threadIdx.x & 1;             // x-corner this lane owns
    const int l  = (threadIdx.x >> 1) & 15;     // level this lane pair owns

    const int   res      = c_res[l];
    const int   res2     = res * res;
    const float sc       = 0.5f * (float)res;
    const bool  use_hash = (l >= 8);
    const float2* __restrict__ tab = p.tab[l];

    // All 32 lanes broadcast-load the same 12 B.
    const float px = __ldg(x + 3 * b + 0);
    const float py = __ldg(x + 3 * b + 1);
    const float pz = __ldg(x + 3 * b + 2);

    // xp = (x + 1) * (res/2) - 0.5, exact f32 op order of the reference.
    const float xp = __fadd_rn(__fmul_rn(__fadd_rn(px, 1.0f), sc), -0.5f);
    const float yp = __fadd_rn(__fmul_rn(__fadd_rn(py, 1.0f), sc), -0.5f);
    const float zp = __fadd_rn(__fmul_rn(__fadd_rn(pz, 1.0f), sc), -0.5f);

    const float fx = floorf(xp), fy = floorf(yp), fz = floorf(zp);
    const int ix = (int)fx, iy = (int)fy, iz = (int)fz;
    const float tx = __fsub_rn(xp, fx);
    const float ty = __fsub_rn(yp, fy);
    const float tz = __fsub_rn(zp, fz);
    const float ux = __fsub_rn(1.0f, tx);
    const float uy = __fsub_rn(1.0f, ty);
    const float uz = __fsub_rn(1.0f, tz);

    // This lane's x-corner (shared by its 4 corners).
    const int   cx = ix + ox;
    const float wx = ox ? tx : ux;
    const bool  vx = ((unsigned)cx < (unsigned)res);
    const unsigned hx = (unsigned)cx;           // cx * PRIME0(=1)

    // Per-dim incremental index components (strength-reduced).
    const unsigned hy0 = (unsigned)iy * P1, hy1 = hy0 + P1;
    const unsigned hz0 = (unsigned)iz * P2, hz1 = hz0 + P2;
    const int      dy0 = iy * res,  dy1 = dy0 + res;
    const int      dz0 = iz * res2, dz1 = dz0 + res2;
    const bool vy0 = ((unsigned)iy       < (unsigned)res);
    const bool vy1 = ((unsigned)(iy + 1) < (unsigned)res);
    const bool vz0 = ((unsigned)iz       < (unsigned)res);
    const bool vz1 = ((unsigned)(iz + 1) < (unsigned)res);

    // ---- 4 corners (oy,oz); paired lanes (ox=0/1) coalesce in L1TEX ----
    float    w[4];
    unsigned idx[4];
    #pragma unroll
    for (int cc = 0; cc < 4; ++cc) {
        const int oy = (cc >> 1) & 1, oz = cc & 1;
        const bool valid = vx & (oy ? vy1 : vy0) & (oz ? vz1 : vz0);
        const float ww = __fmul_rn(__fmul_rn(wx, oy ? ty : uy), oz ? tz : uz);
        w[cc] = valid ? ww : 0.0f;

        const unsigned hidx = (hx ^ (oy ? hy1 : hy0) ^ (oz ? hz1 : hz0)) & HMASK;
        const unsigned didx = (unsigned)(cx + (oy ? dy1 : dy0) + (oz ? dz1 : dz0));
        const unsigned ii = use_hash ? hidx : didx;
        idx[cc] = valid ? ii : 0u;
    }

    // ---- batched 4-wide gather (all levels, single LDG path) ----
    float2 e0 = __ldg(&tab[idx[0]]);
    float2 e1 = __ldg(&tab[idx[1]]);
    float2 e2 = __ldg(&tab[idx[2]]);
    float2 e3 = __ldg(&tab[idx[3]]);

    float a0 = fmaf(e0.x, w[0], 0.0f);
    float a1 = fmaf(e0.y, w[0], 0.0f);
    a0 = fmaf(e1.x, w[1], a0);
    a1 = fmaf(e1.y, w[1], a1);
    a0 = fmaf(e2.x, w[2], a0);
    a1 = fmaf(e2.y, w[2], a1);
    a0 = fmaf(e3.x, w[3], a0);
    a1 = fmaf(e3.y, w[3], a1);

    // Pair reduction: even lane accumulates the odd lane's 4 corners.
    a0 += __shfl_xor_sync(0xffffffffu, a0, 1);
    a1 += __shfl_xor_sync(0xffffffffu, a1, 1);

    if (ox == 0) {
        // 16 even lanes store 128 contiguous bytes per warp.
        __stcs(&out[(size_t)b * NLEVELS + l], make_float2(a0, a1));
    }
}

extern "C" void kernel_launch(void* const* d_in, const int* in_sizes, int n_in,
                              void* d_out, int out_size)
{
    const float* x = (const float*)d_in[0];
    Params p;
    #pragma unroll
    for (int l = 0; l < NLEVELS; ++l) {
        p.tab[l] = (const float2*)d_in[1 + l];
    }
    const int B = in_sizes[0] / 3;

    const long long total = (long long)B * 32;          // threads: 1 per item-half
    const int blocks = (int)((total + 255) / 256);
    hashenc_kernel<<<blocks, 256>>>(x, p, (float2*)d_out, B);
}

// round 7
// speedup vs baseline: 2.7393x; 2.7393x over previous
#include <cuda_runtime.h>
#include <stdint.h>

// MultiLevelHybridHashEncoding — instant-NGP hash-grid encoding.
// R6 -> R7: R6 regressed from register spills (32-reg cap -> local-memory
// traffic, DRAM x5). Revert to the R5 winner (smem levels 0..1, persistent
// 2 CTA x 768 thr, x-prefetch, pair-coalesced gathers, shfl pair-reduce) and
// apply ONE change: strength-reduced per-dim index + validity precomputation
// (hash components hy/hz, dense dy/dz, bounds bits computed once per point).

#define NLEVELS 16
#define TPB 768

#define L0_N 4096    // 16^3
#define L1_N 8000    // 20^3
#define SMEM_BYTES ((L0_N + L1_N) * 8)   // 96768 B per CTA

#define P1 2654435761u
#define P2 805459861u
#define HMASK 0x7FFFFu

struct Params {
    const float2* tab[NLEVELS];
};

__device__ __constant__ int c_res[NLEVELS] = {
    16, 20, 25, 32, 40, 50, 64, 80, 101, 128, 161, 203, 256, 322, 406, 512
};

extern __shared__ float2 s_tab[];

__global__ void __launch_bounds__(TPB, 2)
hashenc_kernel(const float* __restrict__ x, Params p,
               float2* __restrict__ out, int B)
{
    // ---- cooperative smem fill: levels 0..1, coalesced ----
    {
        const float2* __restrict__ t0 = p.tab[0];
        const float2* __restrict__ t1 = p.tab[1];
        for (int i = threadIdx.x; i < L0_N; i += TPB) s_tab[i] = __ldg(t0 + i);
        for (int i = threadIdx.x; i < L1_N; i += TPB) s_tab[L0_N + i] = __ldg(t1 + i);
    }
    __syncthreads();

    // Thread = (point, level, x-half). 32 consecutive threads = 1 point.
    const int   ox       = threadIdx.x & 1;        // x-corner this lane owns
    const int   l        = (threadIdx.x >> 1) & 15;
    const int   res      = c_res[l];
    const int   res2     = res * res;
    const float sc       = 0.5f * (float)res;
    const bool  in_smem  = (l < 2);
    const bool  use_hash = (l >= 8);
    const float2* __restrict__ gtab = p.tab[l];
    const float2* __restrict__ stab = s_tab + (l == 0 ? 0 : L0_N);

    const int total  = B * NLEVELS * 2;             // (point, level, half) items
    const int stride = gridDim.x * TPB;
    int tid = blockIdx.x * TPB + threadIdx.x;
    if (tid >= total) return;

    // Prologue: load first point (all 32 lanes broadcast the same 12 B).
    float px, py, pz;
    {
        const int b = tid >> 5;
        px = __ldg(x + 3 * b + 0);
        py = __ldg(x + 3 * b + 1);
        pz = __ldg(x + 3 * b + 2);
    }

    while (true) {
        // ---- prefetch next iteration's point ----
        const int tid_n = tid + stride;
        float nx = 0.f, ny = 0.f, nz = 0.f;
        if (tid_n < total) {
            const int bn = tid_n >> 5;
            nx = __ldg(x + 3 * bn + 0);
            ny = __ldg(x + 3 * bn + 1);
            nz = __ldg(x + 3 * bn + 2);
        }

        const int b = tid >> 5;

        // xp = (x + 1) * (res/2) - 0.5, exact f32 op order of the reference.
        const float xp = __fadd_rn(__fmul_rn(__fadd_rn(px, 1.0f), sc), -0.5f);
        const float yp = __fadd_rn(__fmul_rn(__fadd_rn(py, 1.0f), sc), -0.5f);
        const float zp = __fadd_rn(__fmul_rn(__fadd_rn(pz, 1.0f), sc), -0.5f);

        const float fx = floorf(xp), fy = floorf(yp), fz = floorf(zp);
        const int ix = (int)fx, iy = (int)fy, iz = (int)fz;
        const float tx = __fsub_rn(xp, fx);
        const float ty = __fsub_rn(yp, fy);
        const float tz = __fsub_rn(zp, fz);
        const float ux = __fsub_rn(1.0f, tx);
        const float uy = __fsub_rn(1.0f, ty);
        const float uz = __fsub_rn(1.0f, tz);

        // This lane's x-corner (shared by its 4 corners).
        const int   cx = ix + ox;
        const float wx = ox ? tx : ux;
        const bool  vx = ((unsigned)cx < (unsigned)res);
        const unsigned hx = (unsigned)cx;           // cx * PRIME0(=1)

        // Per-dim incremental components (computed once per point).
        const unsigned hy0 = (unsigned)iy * P1, hy1 = hy0 + P1;
        const unsigned hz0 = (unsigned)iz * P2, hz1 = hz0 + P2;
        const int      dy0 = iy * res,  dy1 = dy0 + res;
        const int      dz0 = iz * res2, dz1 = dz0 + res2;
        const bool vy0 = ((unsigned)iy       < (unsigned)res);
        const bool vy1 = ((unsigned)(iy + 1) < (unsigned)res);
        const bool vz0 = ((unsigned)iz       < (unsigned)res);
        const bool vz1 = ((unsigned)(iz + 1) < (unsigned)res);

        // ---- 4 corners (oy,oz); paired lanes (ox=0/1) coalesce in L1TEX ----
        float    w[4];
        unsigned idx[4];
        #pragma unroll
        for (int cc = 0; cc < 4; ++cc) {
            const int oy = (cc >> 1) & 1, oz = cc & 1;
            const bool valid = vx & (oy ? vy1 : vy0) & (oz ? vz1 : vz0);
            const float ww = __fmul_rn(__fmul_rn(wx, oy ? ty : uy), oz ? tz : uz);
            w[cc] = valid ? ww : 0.0f;

            const unsigned hidx = (hx ^ (oy ? hy1 : hy0) ^ (oz ? hz1 : hz0)) & HMASK;
            const unsigned didx = (unsigned)(cx + (oy ? dy1 : dy0) + (oz ? dz1 : dz0));
            const unsigned ii = use_hash ? hidx : didx;
            idx[cc] = valid ? ii : 0u;
        }

        // ---- batched 4-wide gather ----
        float2 e[4];
        if (in_smem) {
            #pragma unroll
            for (int cc = 0; cc < 4; ++cc) e[cc] = stab[idx[cc]];
        } else {
            #pragma unroll
            for (int cc = 0; cc < 4; ++cc) e[cc] = __ldg(&gtab[idx[cc]]);
        }

        float a0 = 0.0f, a1 = 0.0f;
        #pragma unroll
        for (int cc = 0; cc < 4; ++cc) {
            a0 = fmaf(e[cc].x, w[cc], a0);
            a1 = fmaf(e[cc].y, w[cc], a1);
        }

        // Pair reduction: even lane accumulates the odd lane's 4 corners.
        a0 += __shfl_xor_sync(0xffffffffu, a0, 1);
        a1 += __shfl_xor_sync(0xffffffffu, a1, 1);

        if (ox == 0) {
            // 16 even lanes store 128 contiguous bytes per warp.
            __stcs(&out[(size_t)b * NLEVELS + l], make_float2(a0, a1));
        }

        if (tid_n >= total) break;
        tid = tid_n;
        px = nx; py = ny; pz = nz;
    }
}

extern "C" void kernel_launch(void* const* d_in, const int* in_sizes, int n_in,
                              void* d_out, int out_size)
{
    const float* x = (const float*)d_in[0];
    Params p;
    #pragma unroll
    for (int l = 0; l < NLEVELS; ++l) {
        p.tab[l] = (const float2*)d_in[1 + l];
    }
    const int B = in_sizes[0] / 3;

    cudaFuncSetAttribute(hashenc_kernel,
                         cudaFuncAttributeMaxDynamicSharedMemorySize, SMEM_BYTES);

    int sms = 148;
    cudaDeviceGetAttribute(&sms, cudaDevAttrMultiProcessorCount, 0);

    hashenc_kernel<<<2 * sms, TPB, SMEM_BYTES>>>(x, p, (float2*)d_out, B);
}